// round 15
// baseline (speedup 1.0000x reference)
#include <cuda_runtime.h>
#include <cuda_bf16.h>
#include <cstdint>
#include <cstddef>
#include <math.h>

#define B_N 32
#define C_N 64
#define M_N 16384
#define CH_N 16
#define MC_N (M_N / CH_N)     /* 1024 m per chunk */
#define KT_N 64               /* m per stage tile */
#define NT_N (MC_N / KT_N)    /* 16 stages per CTA */

// Scratch (device globals: no allocation allowed)
__device__ float g_pgram[B_N * CH_N * 4096]; // P partial grams (block-upper-tri)
__device__ float g_cov[B_N * 4096];          // reduced (uncentered) grams
__device__ float g_prow[B_N * CH_N * C_N];   // partial row sums
__device__ float g_y[B_N * C_N];             // gate values

// Swizzled layout for ns_pass 64-float rows
__device__ __forceinline__ int swz64(int r, int c) {
    return r * 64 + (((c >> 2) ^ ((r >> 2) & 7)) << 2) + (c & 3);
}

__device__ __forceinline__ uint32_t smem_u32(const void* p) {
    uint32_t a;
    asm("{ .reg .u64 t; cvta.to.shared.u64 t, %1; cvt.u32.u64 %0, t; }" : "=r"(a) : "l"(p));
    return a;
}
__device__ __forceinline__ void ldsm4(uint32_t* r, uint32_t addr) {
    asm volatile("ldmatrix.sync.aligned.m8n8.x4.shared.b16 {%0,%1,%2,%3}, [%4];"
                 : "=r"(r[0]), "=r"(r[1]), "=r"(r[2]), "=r"(r[3]) : "r"(addr));
}
__device__ __forceinline__ void mma16816(float* d, const uint32_t* a, const uint32_t* b) {
    asm volatile(
        "mma.sync.aligned.m16n8k16.row.col.f32.bf16.bf16.f32 "
        "{%0,%1,%2,%3}, {%4,%5,%6,%7}, {%8,%9}, {%0,%1,%2,%3};"
        : "+f"(d[0]), "+f"(d[1]), "+f"(d[2]), "+f"(d[3])
        : "r"(a[0]), "r"(a[1]), "r"(a[2]), "r"(a[3]), "r"(b[0]), "r"(b[1]));
}

// Stage buffer: 64 rows x 64 bf16, 128 B/row, XOR-swizzled 16B chunks
#define STAGE_BYTES 8192

// ---------------------------------------------------------------------------
// Pass 1: read x,prev -> d, row sums, pure-bf16 mma.sync gram (upper triangle).
// KT_N=64 stage -> pf[4] (16 regs) -> fits 3 CTAs/SM without spills.
// ---------------------------------------------------------------------------
__global__ __launch_bounds__(256, 3) void cov_pass_kernel(
    const float* __restrict__ x, const float* __restrict__ prev)
{
    __shared__ char stage[STAGE_BYTES];
    const uint32_t smb = smem_u32(stage);
    const int blk = blockIdx.x;       // b*CH + ch
    const int b = blk >> 4;
    const int ch = blk & 15;
    const int tid = threadIdx.x;
    const int warp = tid >> 5, lane = tid & 31;
    const long base = (long)b * C_N * M_N + (long)ch * MC_N;

    // Upper-triangle 16x16 block assignment over 8 warps
    const int ib0 = (warp < 4) ? 0 : (warp < 7) ? 1 : 2;
    const int jb0 = (warp < 4) ? warp : (warp < 7) ? (warp - 3) : 2;
    const bool has2 = (warp < 2);
    const int ib1 = 2 + warp;
    const int jb1 = 3;

    const int q = lane >> 3, r = lane & 7;

    float acc0[8], acc1[8];
#pragma unroll
    for (int i = 0; i < 8; i++) { acc0[i] = 0.0f; acc1[i] = 0.0f; }
    float rowacc[4];
#pragma unroll
    for (int k = 0; k < 4; k++) rowacc[k] = 0.0f;

    float4 pf[4]; // prefetched diffs (16 regs)

    auto prefetch = [&](int s) {
        const long m0 = base + (long)s * KT_N;
#pragma unroll
        for (int k = 0; k < 4; k++) {
            int f = tid + k * 256;
            int c = f >> 4;        // row 0..63 (16 float4 per 64-col row)
            int m4i = f & 15;
            long g = m0 + (long)c * M_N;
            const float4 xv = reinterpret_cast<const float4*>(x + g)[m4i];
            const float4 pv = reinterpret_cast<const float4*>(prev + g)[m4i];
            float4 d;
            d.x = xv.x - pv.x; d.y = xv.y - pv.y;
            d.z = xv.z - pv.z; d.w = xv.w - pv.w;
            rowacc[k] += (d.x + d.y) + (d.z + d.w);
            pf[k] = d;
        }
    };

    // 128 B/row swizzle: chunk c16 (0..7) XOR (row&7)
    auto adrA = [&](int rowbase, int ks) {
        int row = rowbase + ((q & 1) << 3) + r;
        int c16 = 2 * ks + (q >> 1);
        return smb + (uint32_t)(row * 128 + ((c16 ^ (row & 7)) << 4));
    };
    auto adrB = [&](int jbase, int ks) {
        int row = jbase + ((q >> 1) << 3) + r;
        int c16 = 2 * ks + (q & 1);
        return smb + (uint32_t)(row * 128 + ((c16 ^ (row & 7)) << 4));
    };

    prefetch(0);

    for (int s = 0; s < NT_N; s++) {
        __syncthreads(); // buffer free
#pragma unroll
        for (int k = 0; k < 4; k++) {
            int f = tid + k * 256;
            int c = f >> 4;
            int m4i = f & 15;
            float4 d = pf[k];
            __nv_bfloat162 h01 = __float22bfloat162_rn(make_float2(d.x, d.y));
            __nv_bfloat162 h23 = __float22bfloat162_rn(make_float2(d.z, d.w));
            uint32_t off = (uint32_t)(c * 128) + ((((uint32_t)m4i >> 1) ^ (uint32_t)(c & 7)) << 4)
                         + ((m4i & 1) << 3);
            *reinterpret_cast<uint2*>(stage + off) =
                make_uint2(*reinterpret_cast<unsigned*>(&h01), *reinterpret_cast<unsigned*>(&h23));
        }
        __syncthreads(); // tile ready
        if (s + 1 < NT_N) prefetch(s + 1); // LDGs issued under compute

#pragma unroll
        for (int ks = 0; ks < 4; ks++) {
            uint32_t a[4], bb[4];
            ldsm4(a, adrA(ib0 * 16, ks));
            ldsm4(bb, adrB(jb0 * 16, ks));
            mma16816(acc0 + 0, a, bb + 0);
            mma16816(acc0 + 4, a, bb + 2);
            if (has2) {
                uint32_t a2[4], b2[4];
                ldsm4(a2, adrA(ib1 * 16, ks));
                ldsm4(b2, adrB(jb1 * 16, ks));
                mma16816(acc1 + 0, a2, b2 + 0);
                mma16816(acc1 + 4, a2, b2 + 2);
            }
        }
    }

    // Readout 16x16 block(s) to partial-gram slot
    {
        float* dst = g_pgram + (size_t)blk * 4096;
        int g = lane >> 2, tc = (lane & 3) * 2;
#pragma unroll
        for (int t = 0; t < 2; t++) {
            int j = jb0 * 16 + t * 8 + tc;
            *reinterpret_cast<float2*>(dst + (ib0 * 16 + g) * 64 + j) =
                make_float2(acc0[t * 4 + 0], acc0[t * 4 + 1]);
            *reinterpret_cast<float2*>(dst + (ib0 * 16 + g + 8) * 64 + j) =
                make_float2(acc0[t * 4 + 2], acc0[t * 4 + 3]);
        }
        if (has2) {
#pragma unroll
            for (int t = 0; t < 2; t++) {
                int j = jb1 * 16 + t * 8 + tc;
                *reinterpret_cast<float2*>(dst + (ib1 * 16 + g) * 64 + j) =
                    make_float2(acc1[t * 4 + 0], acc1[t * 4 + 1]);
                *reinterpret_cast<float2*>(dst + (ib1 * 16 + g + 8) * 64 + j) =
                    make_float2(acc1[t * 4 + 2], acc1[t * 4 + 3]);
            }
        }
    }

    // Row sums: 16-thread half-groups share a channel per k
#pragma unroll
    for (int k = 0; k < 4; k++) {
        float v = rowacc[k];
#pragma unroll
        for (int o = 8; o; o >>= 1) v += __shfl_xor_sync(0xffffffffu, v, o);
        if ((lane & 15) == 0)
            g_prow[blk * 64 + (tid >> 4) + 16 * k] = v;
    }
}

// ---------------------------------------------------------------------------
// Pass 1.5: reduce partial slots -> g_cov, mirroring the upper triangle.
// ---------------------------------------------------------------------------
__global__ __launch_bounds__(256) void reduce_kernel()
{
    const int b = blockIdx.x >> 2;
    const int seg = blockIdx.x & 3;
    const int i4 = seg * 256 + threadIdx.x;
    const int i = i4 >> 4, j0 = (i4 & 15) * 4;
    const bool upper = (i >> 4) <= (j0 >> 4);
    const float* base = g_pgram + (size_t)b * CH_N * 4096;
    float4 g = make_float4(0.f, 0.f, 0.f, 0.f);
    if (upper) {
#pragma unroll 4
        for (int ch = 0; ch < CH_N; ch++) {
            float4 p = *reinterpret_cast<const float4*>(base + (size_t)ch * 4096 + i * 64 + j0);
            g.x += p.x; g.y += p.y; g.z += p.z; g.w += p.w;
        }
    } else {
#pragma unroll 4
        for (int ch = 0; ch < CH_N; ch++) {
            const float* P = base + (size_t)ch * 4096;
            g.x += P[(j0 + 0) * 64 + i];
            g.y += P[(j0 + 1) * 64 + i];
            g.z += P[(j0 + 2) * 64 + i];
            g.w += P[(j0 + 3) * 64 + i];
        }
    }
    reinterpret_cast<float4*>(g_cov + (size_t)b * 4096)[i4] = g;
}

// ---------------------------------------------------------------------------
// 64x64 shared-memory matmul, 512 threads, 2x4 thread tile.
// B read row-wise (valid: symmetric). MODE: 0 plain, 1 0.5*(3I-P), 2 3I-P, 3 scale*P
// ---------------------------------------------------------------------------
template <int MODE>
__device__ __forceinline__ void mm64(float* __restrict__ D,
    const float* __restrict__ A, const float* __restrict__ Bm,
    int tx, int ty, float scale)
{
    __syncthreads();
    const float4* A4 = reinterpret_cast<const float4*>(A);
    const float4* B4 = reinterpret_cast<const float4*>(Bm);
    const int keyA = (ty >> 1) & 7;
    const int keyB = tx & 7;
    float acc[2][4];
#pragma unroll
    for (int i = 0; i < 2; i++)
#pragma unroll
        for (int j = 0; j < 4; j++) acc[i][j] = 0.0f;
#pragma unroll
    for (int k4 = 0; k4 < 16; k4++) {
        float4 a[2], bb[4];
#pragma unroll
        for (int i = 0; i < 2; i++) a[i] = A4[(2 * ty + i) * 16 + (k4 ^ keyA)];
#pragma unroll
        for (int j = 0; j < 4; j++) bb[j] = B4[(4 * tx + j) * 16 + (k4 ^ keyB)];
#pragma unroll
        for (int i = 0; i < 2; i++)
#pragma unroll
            for (int j = 0; j < 4; j++) {
                acc[i][j] = fmaf(a[i].x, bb[j].x, acc[i][j]);
                acc[i][j] = fmaf(a[i].y, bb[j].y, acc[i][j]);
                acc[i][j] = fmaf(a[i].z, bb[j].z, acc[i][j]);
                acc[i][j] = fmaf(a[i].w, bb[j].w, acc[i][j]);
            }
    }
    __syncthreads();
    float4* D4 = reinterpret_cast<float4*>(D);
#pragma unroll
    for (int i = 0; i < 2; i++) {
        int rr = 2 * ty + i;
        float fv[4];
#pragma unroll
        for (int j = 0; j < 4; j++) {
            int cc = 4 * tx + j;
            float t = acc[i][j];
            if (MODE == 1) t = 0.5f * ((rr == cc ? 3.0f : 0.0f) - t);
            else if (MODE == 2) t = (rr == cc ? 3.0f : 0.0f) - t;
            else if (MODE == 3) t = t * scale;
            fv[j] = t;
        }
        D4[rr * 16 + (tx ^ keyA)] = make_float4(fv[0], fv[1], fv[2], fv[3]);
    }
}

// ---------------------------------------------------------------------------
// Pass 2: g_cov -> centered cov -> Newton-Schulz sqrtm -> means -> MLP gate
// ---------------------------------------------------------------------------
__global__ __launch_bounds__(512) void ns_pass_kernel(
    const float* __restrict__ w1, const float* __restrict__ b1v,
    const float* __restrict__ w2, const float* __restrict__ b2v)
{
    extern __shared__ float sh[];
    float* An = sh;
    float* Ym = sh + 4096;
    float* Zm = sh + 8192;
    float* Tm = sh + 12288;
    float* scr = sh + 16384;
    const int b = blockIdx.x;
    const int tid = threadIdx.x;
    const int tx = tid & 15, ty = tid >> 4;
    const int lane = tid & 31;

    if (tid < 64) {
        float rsum = 0.0f;
#pragma unroll
        for (int ch = 0; ch < CH_N; ch++) rsum += g_prow[(b * CH_N + ch) * 64 + tid];
        scr[tid] = rsum;
    }
    __syncthreads();
    const float invM = 1.0f / (float)M_N;
    {
        const float4* cv4 = reinterpret_cast<const float4*>(g_cov + (size_t)b * 4096);
        for (int i4 = tid; i4 < 1024; i4 += 512) {
            float4 g = cv4[i4];
            int i = i4 >> 4, j0 = (i4 & 15) * 4;
            float si = scr[i] * invM;
            float4 v;
            v.x = (g.x - si * scr[j0 + 0]) * invM;
            v.y = (g.y - si * scr[j0 + 1]) * invM;
            v.z = (g.z - si * scr[j0 + 2]) * invM;
            v.w = (g.w - si * scr[j0 + 3]) * invM;
            int o = i * 64 + (((j0 >> 2) ^ ((i >> 2) & 7)) << 2);
            *reinterpret_cast<float4*>(An + o) = v;
        }
    }
    __syncthreads();
    if (tid < 64) {
        float t = An[swz64(tid, tid)];
#pragma unroll
        for (int o = 16; o; o >>= 1) t += __shfl_xor_sync(0xffffffffu, t, o);
        if (lane == 0) scr[72 + (tid >> 5)] = t;
    }
    __syncthreads();
    if (tid == 0) scr[64] = scr[72] + scr[73];
    __syncthreads();
    const float normA = scr[64];
    const float invN = 1.0f / normA;
    for (int idx = tid; idx < 4096; idx += 512) An[idx] *= invN;
    __syncthreads();
    for (int idx = tid; idx < 4096; idx += 512) {
        int i = idx >> 6, j = idx & 63;
        int o = swz64(i, j);
        Tm[o] = 0.5f * ((i == j ? 3.0f : 0.0f) - An[o]);
    }
    mm64<0>(Ym, An, Tm, tx, ty, 1.0f);   // Y = An @ ZY
    for (int idx = tid; idx < 4096; idx += 512) Zm[idx] = Tm[idx];
#pragma unroll 1
    for (int it = 0; it < 3; it++) {
        mm64<1>(Tm, Zm, Ym, tx, ty, 1.0f); // ZY = 0.5*(3I - Z@Y)
        mm64<0>(Ym, Ym, Tm, tx, ty, 1.0f); // Y = Y @ ZY
        mm64<0>(Zm, Tm, Zm, tx, ty, 1.0f); // Z = ZY @ Z
    }
    mm64<2>(Tm, Zm, Ym, tx, ty, 1.0f);                // T = 3I - Z@Y
    mm64<3>(An, Ym, Tm, tx, ty, 0.5f * sqrtf(normA)); // result

    __syncthreads();
    // s[c] = mean over rows; 8 threads per column, 8 rows each
    {
        int c = tid & 63, seg = tid >> 6;
        float sv = 0.0f;
        for (int rr = seg * 8; rr < seg * 8 + 8; rr++) sv += An[swz64(rr, c)];
        if (seg == 0) scr[128 + c] = 0.0f;
        __syncthreads();
        atomicAdd(&scr[128 + c], sv);
    }
    __syncthreads();
    if (tid < 64) scr[tid] = scr[128 + tid] * (1.0f / 64.0f);
    __syncthreads();
    if (tid < 8) {
        float h = b1v[tid];
        for (int c = 0; c < 64; c++) h = fmaf(w1[tid * 64 + c], scr[c], h);
        scr[96 + tid] = fmaxf(h, 0.0f);
    }
    __syncthreads();
    if (tid < 64) {
        float t = b2v[tid];
#pragma unroll
        for (int o = 0; o < 8; o++) t = fmaf(w2[tid * 8 + o], scr[96 + o], t);
        g_y[b * 64 + tid] = 1.0f / (1.0f + __expf(-t));
    }
}

// ---------------------------------------------------------------------------
// Pass 3: out = (x - prev) * y[b,c]   (high-MLP streaming; 8 float4/thread)
// ---------------------------------------------------------------------------
__global__ __launch_bounds__(256) void scale_kernel(
    const float* __restrict__ x, const float* __restrict__ prev,
    float* __restrict__ out)
{
    const long base = (long)blockIdx.x * 2048;
    const float v = g_y[base >> 12];
    const float4* x4 = reinterpret_cast<const float4*>(x);
    const float4* p4 = reinterpret_cast<const float4*>(prev);
    float4* o4 = reinterpret_cast<float4*>(out);
#pragma unroll
    for (int k = 0; k < 8; k++) {
        long i = base + threadIdx.x + k * 256;
        float4 a = x4[i];
        float4 p = p4[i];
        float4 d;
        d.x = (a.x - p.x) * v; d.y = (a.y - p.y) * v;
        d.z = (a.z - p.z) * v; d.w = (a.w - p.w) * v;
        o4[i] = d;
    }
}

extern "C" void kernel_launch(void* const* d_in, const int* in_sizes, int n_in,
                              void* d_out, int out_size)
{
    const float* prev = (const float*)d_in[0];
    const float* x    = (const float*)d_in[1];
    const float* w1   = (const float*)d_in[2];
    const float* b1   = (const float*)d_in[3];
    const float* w2   = (const float*)d_in[4];
    const float* b2   = (const float*)d_in[5];
    float* out = (float*)d_out;

    cudaFuncSetAttribute(ns_pass_kernel,
                         cudaFuncAttributeMaxDynamicSharedMemorySize, 16640 * 4);

    cov_pass_kernel<<<B_N * CH_N, 256>>>(x, prev);
    reduce_kernel<<<B_N * 4, 256>>>();
    ns_pass_kernel<<<B_N, 512, 16640 * 4>>>(w1, b1, w2, b2);
    scale_kernel<<<(B_N * C_N * M_N) / 8192, 256>>>(x, prev, out);
}

// round 16
// speedup vs baseline: 1.1400x; 1.1400x over previous
#include <cuda_runtime.h>
#include <cuda_bf16.h>
#include <cstdint>
#include <cstddef>
#include <math.h>

#define B_N 32
#define C_N 64
#define M_N 16384
#define CH_N 16
#define MC_N (M_N / CH_N)     /* 1024 m per chunk */
#define KT_N 64               /* m per stage tile */
#define NT_N (MC_N / KT_N)    /* 16 stages per CTA */

// Scratch (device globals: no allocation allowed)
__device__ float g_pgram[B_N * CH_N * 4096]; // P partial grams (block-upper-tri)
__device__ float g_cov[B_N * 4096];          // reduced (uncentered) grams
__device__ float g_prow[B_N * CH_N * C_N];   // partial row sums
__device__ float g_y[B_N * C_N];             // gate values

// Swizzled layout for ns_pass 64-float rows
__device__ __forceinline__ int swz64(int r, int c) {
    return r * 64 + (((c >> 2) ^ ((r >> 2) & 7)) << 2) + (c & 3);
}

__device__ __forceinline__ uint32_t smem_u32(const void* p) {
    uint32_t a;
    asm("{ .reg .u64 t; cvta.to.shared.u64 t, %1; cvt.u32.u64 %0, t; }" : "=r"(a) : "l"(p));
    return a;
}
__device__ __forceinline__ void ldsm4(uint32_t* r, uint32_t addr) {
    asm volatile("ldmatrix.sync.aligned.m8n8.x4.shared.b16 {%0,%1,%2,%3}, [%4];"
                 : "=r"(r[0]), "=r"(r[1]), "=r"(r[2]), "=r"(r[3]) : "r"(addr));
}
__device__ __forceinline__ void mma16816(float* d, const uint32_t* a, const uint32_t* b) {
    asm volatile(
        "mma.sync.aligned.m16n8k16.row.col.f32.bf16.bf16.f32 "
        "{%0,%1,%2,%3}, {%4,%5,%6,%7}, {%8,%9}, {%0,%1,%2,%3};"
        : "+f"(d[0]), "+f"(d[1]), "+f"(d[2]), "+f"(d[3])
        : "r"(a[0]), "r"(a[1]), "r"(a[2]), "r"(a[3]), "r"(b[0]), "r"(b[1]));
}
__device__ __forceinline__ void cp16(uint32_t dst, const void* src) {
    asm volatile("cp.async.cg.shared.global [%0], [%1], 16;" :: "r"(dst), "l"(src) : "memory");
}

// Dynamic smem layout:
//   raw stage i (i=0..2): x at i*32768, prev at i*32768+16384  (16 KB each, linear)
//   bf16 tile at 98304 (64 rows x 128 B, XOR-swizzled 16B chunks)
#define RAW_STAGE 32768
#define TILE_OFF 98304
#define COV_SMEM (TILE_OFF + 8192)

// ---------------------------------------------------------------------------
// Pass 1: cp.async 3-deep raw pipeline -> diff/rowsum/bf16 -> mma gram
// (upper triangle, 10 blocks over 8 warps).
// ---------------------------------------------------------------------------
__global__ __launch_bounds__(256) void cov_pass_kernel(
    const float* __restrict__ x, const float* __restrict__ prev)
{
    extern __shared__ char sm[];
    const uint32_t smb = smem_u32(sm);
    const int blk = blockIdx.x;       // b*CH + ch
    const int b = blk >> 4;
    const int ch = blk & 15;
    const int tid = threadIdx.x;
    const int warp = tid >> 5, lane = tid & 31;
    const long base = (long)b * C_N * M_N + (long)ch * MC_N;

    // Upper-triangle 16x16 block assignment over 8 warps
    const int ib0 = (warp < 4) ? 0 : (warp < 7) ? 1 : 2;
    const int jb0 = (warp < 4) ? warp : (warp < 7) ? (warp - 3) : 2;
    const bool has2 = (warp < 2);
    const int ib1 = 2 + warp;
    const int jb1 = 3;

    const int q = lane >> 3, r = lane & 7;

    float acc0[8], acc1[8];
#pragma unroll
    for (int i = 0; i < 8; i++) { acc0[i] = 0.0f; acc1[i] = 0.0f; }
    float rowacc[4];
#pragma unroll
    for (int k = 0; k < 4; k++) rowacc[k] = 0.0f;

    auto issue_stage = [&](int s) {
        const long m0 = base + (long)s * KT_N;
        const uint32_t xb = smb + (uint32_t)((s % 3) * RAW_STAGE);
        const uint32_t pb = xb + 16384u;
#pragma unroll
        for (int k = 0; k < 4; k++) {
            int f = tid + k * 256;
            int c = f >> 4;        // row 0..63
            int ci = f & 15;       // float4 within row
            long g = m0 + (long)c * M_N + ci * 4;
            cp16(xb + (uint32_t)f * 16u, x + g);
            cp16(pb + (uint32_t)f * 16u, prev + g);
        }
    };

    // bf16-tile addresses (128 B/row, chunk XOR (row&7))
    auto adrA = [&](int rowbase, int ks) {
        int row = rowbase + ((q & 1) << 3) + r;
        int c16 = 2 * ks + (q >> 1);
        return smb + TILE_OFF + (uint32_t)(row * 128 + ((c16 ^ (row & 7)) << 4));
    };
    auto adrB = [&](int jbase, int ks) {
        int row = jbase + ((q >> 1) << 3) + r;
        int c16 = 2 * ks + (q & 1);
        return smb + TILE_OFF + (uint32_t)(row * 128 + ((c16 ^ (row & 7)) << 4));
    };

    // Prologue: fill 3 stages
#pragma unroll
    for (int ps = 0; ps < 3; ps++) {
        issue_stage(ps);
        asm volatile("cp.async.commit_group;" ::: "memory");
    }

    for (int s = 0; s < NT_N; s++) {
        // Oldest of the 3 pending groups (stage s) complete
        asm volatile("cp.async.wait_group 2;" ::: "memory");

        // Consume raw (each thread reads exactly what it cp.async'd)
        const char* xb = sm + (s % 3) * RAW_STAGE;
        const char* pb = xb + 16384;
        uint2 hv[4];
#pragma unroll
        for (int k = 0; k < 4; k++) {
            int f = tid + k * 256;
            float4 xv = *reinterpret_cast<const float4*>(xb + f * 16);
            float4 pv = *reinterpret_cast<const float4*>(pb + f * 16);
            float4 d;
            d.x = xv.x - pv.x; d.y = xv.y - pv.y;
            d.z = xv.z - pv.z; d.w = xv.w - pv.w;
            rowacc[k] += (d.x + d.y) + (d.z + d.w);
            __nv_bfloat162 h01 = __float22bfloat162_rn(make_float2(d.x, d.y));
            __nv_bfloat162 h23 = __float22bfloat162_rn(make_float2(d.z, d.w));
            hv[k] = make_uint2(*reinterpret_cast<unsigned*>(&h01),
                               *reinterpret_cast<unsigned*>(&h23));
        }

        __syncthreads();  // MMA(s-1) done reading bf16 tile
#pragma unroll
        for (int k = 0; k < 4; k++) {
            int f = tid + k * 256;
            int c = f >> 4;
            int m4i = f & 15;
            uint32_t off = (uint32_t)(c * 128) + ((((uint32_t)m4i >> 1) ^ (uint32_t)(c & 7)) << 4)
                         + ((m4i & 1) << 3);
            *reinterpret_cast<uint2*>(sm + TILE_OFF + off) = hv[k];
        }
        __syncthreads();  // tile visible; raw buffer s%3 fully consumed

        // Refill the buffer just consumed (empty commit keeps group algebra uniform)
        if (s + 3 < NT_N) issue_stage(s + 3);
        asm volatile("cp.async.commit_group;" ::: "memory");

        // MMA phase
#pragma unroll
        for (int ks = 0; ks < 4; ks++) {
            uint32_t a[4], bb[4];
            ldsm4(a, adrA(ib0 * 16, ks));
            ldsm4(bb, adrB(jb0 * 16, ks));
            mma16816(acc0 + 0, a, bb + 0);
            mma16816(acc0 + 4, a, bb + 2);
            if (has2) {
                uint32_t a2[4], b2[4];
                ldsm4(a2, adrA(ib1 * 16, ks));
                ldsm4(b2, adrB(jb1 * 16, ks));
                mma16816(acc1 + 0, a2, b2 + 0);
                mma16816(acc1 + 4, a2, b2 + 2);
            }
        }
    }

    // Readout 16x16 block(s) to partial-gram slot
    {
        float* dst = g_pgram + (size_t)blk * 4096;
        int g = lane >> 2, tc = (lane & 3) * 2;
#pragma unroll
        for (int t = 0; t < 2; t++) {
            int j = jb0 * 16 + t * 8 + tc;
            *reinterpret_cast<float2*>(dst + (ib0 * 16 + g) * 64 + j) =
                make_float2(acc0[t * 4 + 0], acc0[t * 4 + 1]);
            *reinterpret_cast<float2*>(dst + (ib0 * 16 + g + 8) * 64 + j) =
                make_float2(acc0[t * 4 + 2], acc0[t * 4 + 3]);
        }
        if (has2) {
#pragma unroll
            for (int t = 0; t < 2; t++) {
                int j = jb1 * 16 + t * 8 + tc;
                *reinterpret_cast<float2*>(dst + (ib1 * 16 + g) * 64 + j) =
                    make_float2(acc1[t * 4 + 0], acc1[t * 4 + 1]);
                *reinterpret_cast<float2*>(dst + (ib1 * 16 + g + 8) * 64 + j) =
                    make_float2(acc1[t * 4 + 2], acc1[t * 4 + 3]);
            }
        }
    }

    // Row sums: 16-thread groups share a row per k
#pragma unroll
    for (int k = 0; k < 4; k++) {
        float v = rowacc[k];
#pragma unroll
        for (int o = 8; o; o >>= 1) v += __shfl_xor_sync(0xffffffffu, v, o);
        if ((lane & 15) == 0)
            g_prow[blk * 64 + (tid >> 4) + 16 * k] = v;
    }
}

// ---------------------------------------------------------------------------
// Pass 1.5: reduce partial slots -> g_cov, mirroring the upper triangle.
// ---------------------------------------------------------------------------
__global__ __launch_bounds__(256) void reduce_kernel()
{
    const int b = blockIdx.x >> 2;
    const int seg = blockIdx.x & 3;
    const int i4 = seg * 256 + threadIdx.x;
    const int i = i4 >> 4, j0 = (i4 & 15) * 4;
    const bool upper = (i >> 4) <= (j0 >> 4);
    const float* base = g_pgram + (size_t)b * CH_N * 4096;
    float4 g = make_float4(0.f, 0.f, 0.f, 0.f);
    if (upper) {
#pragma unroll 4
        for (int ch = 0; ch < CH_N; ch++) {
            float4 p = *reinterpret_cast<const float4*>(base + (size_t)ch * 4096 + i * 64 + j0);
            g.x += p.x; g.y += p.y; g.z += p.z; g.w += p.w;
        }
    } else {
#pragma unroll 4
        for (int ch = 0; ch < CH_N; ch++) {
            const float* P = base + (size_t)ch * 4096;
            g.x += P[(j0 + 0) * 64 + i];
            g.y += P[(j0 + 1) * 64 + i];
            g.z += P[(j0 + 2) * 64 + i];
            g.w += P[(j0 + 3) * 64 + i];
        }
    }
    reinterpret_cast<float4*>(g_cov + (size_t)b * 4096)[i4] = g;
}

// ---------------------------------------------------------------------------
// 64x64 shared-memory matmul, 512 threads, 2x4 thread tile.
// B read row-wise (valid: symmetric). MODE: 0 plain, 1 0.5*(3I-P), 2 3I-P, 3 scale*P
// ---------------------------------------------------------------------------
template <int MODE>
__device__ __forceinline__ void mm64(float* __restrict__ D,
    const float* __restrict__ A, const float* __restrict__ Bm,
    int tx, int ty, float scale)
{
    __syncthreads();
    const float4* A4 = reinterpret_cast<const float4*>(A);
    const float4* B4 = reinterpret_cast<const float4*>(Bm);
    const int keyA = (ty >> 1) & 7;
    const int keyB = tx & 7;
    float acc[2][4];
#pragma unroll
    for (int i = 0; i < 2; i++)
#pragma unroll
        for (int j = 0; j < 4; j++) acc[i][j] = 0.0f;
#pragma unroll
    for (int k4 = 0; k4 < 16; k4++) {
        float4 a[2], bb[4];
#pragma unroll
        for (int i = 0; i < 2; i++) a[i] = A4[(2 * ty + i) * 16 + (k4 ^ keyA)];
#pragma unroll
        for (int j = 0; j < 4; j++) bb[j] = B4[(4 * tx + j) * 16 + (k4 ^ keyB)];
#pragma unroll
        for (int i = 0; i < 2; i++)
#pragma unroll
            for (int j = 0; j < 4; j++) {
                acc[i][j] = fmaf(a[i].x, bb[j].x, acc[i][j]);
                acc[i][j] = fmaf(a[i].y, bb[j].y, acc[i][j]);
                acc[i][j] = fmaf(a[i].z, bb[j].z, acc[i][j]);
                acc[i][j] = fmaf(a[i].w, bb[j].w, acc[i][j]);
            }
    }
    __syncthreads();
    float4* D4 = reinterpret_cast<float4*>(D);
#pragma unroll
    for (int i = 0; i < 2; i++) {
        int rr = 2 * ty + i;
        float fv[4];
#pragma unroll
        for (int j = 0; j < 4; j++) {
            int cc = 4 * tx + j;
            float t = acc[i][j];
            if (MODE == 1) t = 0.5f * ((rr == cc ? 3.0f : 0.0f) - t);
            else if (MODE == 2) t = (rr == cc ? 3.0f : 0.0f) - t;
            else if (MODE == 3) t = t * scale;
            fv[j] = t;
        }
        D4[rr * 16 + (tx ^ keyA)] = make_float4(fv[0], fv[1], fv[2], fv[3]);
    }
}

// ---------------------------------------------------------------------------
// Pass 2: g_cov -> centered cov -> Newton-Schulz sqrtm -> means -> MLP gate
// ---------------------------------------------------------------------------
__global__ __launch_bounds__(512) void ns_pass_kernel(
    const float* __restrict__ w1, const float* __restrict__ b1v,
    const float* __restrict__ w2, const float* __restrict__ b2v)
{
    extern __shared__ float sh[];
    float* An = sh;
    float* Ym = sh + 4096;
    float* Zm = sh + 8192;
    float* Tm = sh + 12288;
    float* scr = sh + 16384;
    const int b = blockIdx.x;
    const int tid = threadIdx.x;
    const int tx = tid & 15, ty = tid >> 4;
    const int lane = tid & 31;

    if (tid < 64) {
        float rsum = 0.0f;
#pragma unroll
        for (int ch = 0; ch < CH_N; ch++) rsum += g_prow[(b * CH_N + ch) * 64 + tid];
        scr[tid] = rsum;
    }
    __syncthreads();
    const float invM = 1.0f / (float)M_N;
    {
        const float4* cv4 = reinterpret_cast<const float4*>(g_cov + (size_t)b * 4096);
        for (int i4 = tid; i4 < 1024; i4 += 512) {
            float4 g = cv4[i4];
            int i = i4 >> 4, j0 = (i4 & 15) * 4;
            float si = scr[i] * invM;
            float4 v;
            v.x = (g.x - si * scr[j0 + 0]) * invM;
            v.y = (g.y - si * scr[j0 + 1]) * invM;
            v.z = (g.z - si * scr[j0 + 2]) * invM;
            v.w = (g.w - si * scr[j0 + 3]) * invM;
            int o = i * 64 + (((j0 >> 2) ^ ((i >> 2) & 7)) << 2);
            *reinterpret_cast<float4*>(An + o) = v;
        }
    }
    __syncthreads();
    if (tid < 64) {
        float t = An[swz64(tid, tid)];
#pragma unroll
        for (int o = 16; o; o >>= 1) t += __shfl_xor_sync(0xffffffffu, t, o);
        if (lane == 0) scr[72 + (tid >> 5)] = t;
    }
    __syncthreads();
    if (tid == 0) scr[64] = scr[72] + scr[73];
    __syncthreads();
    const float normA = scr[64];
    const float invN = 1.0f / normA;
    for (int idx = tid; idx < 4096; idx += 512) An[idx] *= invN;
    __syncthreads();
    for (int idx = tid; idx < 4096; idx += 512) {
        int i = idx >> 6, j = idx & 63;
        int o = swz64(i, j);
        Tm[o] = 0.5f * ((i == j ? 3.0f : 0.0f) - An[o]);
    }
    mm64<0>(Ym, An, Tm, tx, ty, 1.0f);   // Y = An @ ZY
    for (int idx = tid; idx < 4096; idx += 512) Zm[idx] = Tm[idx];
#pragma unroll 1
    for (int it = 0; it < 3; it++) {
        mm64<1>(Tm, Zm, Ym, tx, ty, 1.0f); // ZY = 0.5*(3I - Z@Y)
        mm64<0>(Ym, Ym, Tm, tx, ty, 1.0f); // Y = Y @ ZY
        mm64<0>(Zm, Tm, Zm, tx, ty, 1.0f); // Z = ZY @ Z
    }
    mm64<2>(Tm, Zm, Ym, tx, ty, 1.0f);                // T = 3I - Z@Y
    mm64<3>(An, Ym, Tm, tx, ty, 0.5f * sqrtf(normA)); // result

    __syncthreads();
    {
        int c = tid & 63, seg = tid >> 6;
        float sv = 0.0f;
        for (int rr = seg * 8; rr < seg * 8 + 8; rr++) sv += An[swz64(rr, c)];
        if (seg == 0) scr[128 + c] = 0.0f;
        __syncthreads();
        atomicAdd(&scr[128 + c], sv);
    }
    __syncthreads();
    if (tid < 64) scr[tid] = scr[128 + tid] * (1.0f / 64.0f);
    __syncthreads();
    if (tid < 8) {
        float h = b1v[tid];
        for (int c = 0; c < 64; c++) h = fmaf(w1[tid * 64 + c], scr[c], h);
        scr[96 + tid] = fmaxf(h, 0.0f);
    }
    __syncthreads();
    if (tid < 64) {
        float t = b2v[tid];
#pragma unroll
        for (int o = 0; o < 8; o++) t = fmaf(w2[tid * 8 + o], scr[96 + o], t);
        g_y[b * 64 + tid] = 1.0f / (1.0f + __expf(-t));
    }
}

// ---------------------------------------------------------------------------
// Pass 3: out = (x - prev) * y[b,c]   (high-MLP streaming; 8 float4/thread)
// ---------------------------------------------------------------------------
__global__ __launch_bounds__(256) void scale_kernel(
    const float* __restrict__ x, const float* __restrict__ prev,
    float* __restrict__ out)
{
    const long base = (long)blockIdx.x * 2048;
    const float v = g_y[base >> 12];
    const float4* x4 = reinterpret_cast<const float4*>(x);
    const float4* p4 = reinterpret_cast<const float4*>(prev);
    float4* o4 = reinterpret_cast<float4*>(out);
#pragma unroll
    for (int k = 0; k < 8; k++) {
        long i = base + threadIdx.x + k * 256;
        float4 a = x4[i];
        float4 p = p4[i];
        float4 d;
        d.x = (a.x - p.x) * v; d.y = (a.y - p.y) * v;
        d.z = (a.z - p.z) * v; d.w = (a.w - p.w) * v;
        o4[i] = d;
    }
}

extern "C" void kernel_launch(void* const* d_in, const int* in_sizes, int n_in,
                              void* d_out, int out_size)
{
    const float* prev = (const float*)d_in[0];
    const float* x    = (const float*)d_in[1];
    const float* w1   = (const float*)d_in[2];
    const float* b1   = (const float*)d_in[3];
    const float* w2   = (const float*)d_in[4];
    const float* b2   = (const float*)d_in[5];
    float* out = (float*)d_out;

    cudaFuncSetAttribute(cov_pass_kernel,
                         cudaFuncAttributeMaxDynamicSharedMemorySize, COV_SMEM);
    cudaFuncSetAttribute(ns_pass_kernel,
                         cudaFuncAttributeMaxDynamicSharedMemorySize, 16640 * 4);

    cov_pass_kernel<<<B_N * CH_N, 256, COV_SMEM>>>(x, prev);
    reduce_kernel<<<B_N * 4, 256>>>();
    ns_pass_kernel<<<B_N, 512, 16640 * 4>>>(w1, b1, w2, b2);
    scale_kernel<<<(B_N * C_N * M_N) / 8192, 256>>>(x, prev, out);
}